// round 4
// baseline (speedup 1.0000x reference)
#include <cuda_runtime.h>
#include <cstdint>

#define DEVI __device__ __forceinline__

// ---------------------------------------------------------------------------
// Scratch (device globals)
// ---------------------------------------------------------------------------
__device__ float g_q[33554432];     // Q packed A-frags per (bs,qt,kt)
__device__ float g_k[33554432];     // K packed B-frags (k=channel)
__device__ float g_v[33554432];     // V packed B-frags (k=block)
__device__ float g_attn[33554432];  // attention out, packed A-frags (proj input)
__device__ float g_xr[33554432];    // x packed A-frags, tf32-rounded
__device__ float g_wq[786432];      // W_qkv packed B-frags
__device__ float g_wp[262144];      // W_proj packed B-frags

DEVI unsigned f2tf(float f) {
    unsigned u;
    asm("cvt.rna.tf32.f32 %0, %1;" : "=r"(u) : "f"(f));
    return u;
}
DEVI float f2tff(float f) { return __uint_as_float(f2tf(f)); }

DEVI uint32_t smem_u32(const void* p) {
    uint32_t a;
    asm("{ .reg .u64 t; cvta.to.shared.u64 t, %1; cvt.u32.u64 %0, t; }" : "=r"(a) : "l"(p));
    return a;
}
DEVI uint4 lds128(uint32_t a) {
    uint4 v;
    asm volatile("ld.shared.v4.u32 {%0,%1,%2,%3}, [%4];"
                 : "=r"(v.x), "=r"(v.y), "=r"(v.z), "=r"(v.w) : "r"(a));
    return v;
}
DEVI void cp16(uint32_t s, const void* g) {
    asm volatile("cp.async.cg.shared.global [%0], [%1], 16;" :: "r"(s), "l"(g));
}
DEVI void cp_commit() { asm volatile("cp.async.commit_group;"); }
template <int N> DEVI void cp_wait() { asm volatile("cp.async.wait_group %0;" :: "n"(N)); }

// mma.sync m16n8k8 tf32, D += A*B (fp32 accum)
DEVI void mma8(float* d, const uint4& a, unsigned b0, unsigned b1) {
    asm("mma.sync.aligned.m16n8k8.row.col.f32.tf32.tf32.f32 "
        "{%0,%1,%2,%3}, {%4,%5,%6,%7}, {%8,%9}, {%0,%1,%2,%3};"
        : "+f"(d[0]), "+f"(d[1]), "+f"(d[2]), "+f"(d[3])
        : "r"(a.x), "r"(a.y), "r"(a.z), "r"(a.w), "r"(b0), "r"(b1));
}

// ---------------------------------------------------------------------------
// GEMM operand packs (unchanged layout from R3):
// A: per 128-row mtile, per ktile: u = wmo*256 + mfo*128 + kk*32 + l
//    uint4 = {(r,k),(r+8,k),(r,k+4),(r+8,k+4)}, r = wmo*32+mfo*16+(l>>2)
// B: per 128-col ntile, per ktile: u = wno*512 + nfp*128 + kk*32 + l
//    uint4 = {(c,k),(c,k+4),(c+8,k),(c+8,k+4)}, c = wno*64+nfp*16+(l>>2)
// ---------------------------------------------------------------------------
__global__ void pack_x(const float* __restrict__ x, uint4* __restrict__ o) {
    int u = blockIdx.x * 256 + threadIdx.x;
    int l = u & 31, kk = (u >> 5) & 3, mf = (u >> 7) & 1, wm = (u >> 8) & 3;
    int kt = (u >> 10) & 15, mt = u >> 14;
    int r = mt * 128 + wm * 32 + mf * 16 + (l >> 2);
    int k = kt * 32 + kk * 8 + (l & 3);
    const float* p = x + (size_t)r * 512 + k;
    uint4 v;
    v.x = f2tf(p[0]);
    v.y = f2tf(p[8 * 512]);
    v.z = f2tf(p[4]);
    v.w = f2tf(p[8 * 512 + 4]);
    o[u] = v;
}

template <int NTOT>
__global__ void pack_w(const float* __restrict__ W, uint4* __restrict__ o) {
    int u = blockIdx.x * 256 + threadIdx.x;
    int l = u & 31, kk = (u >> 5) & 3, nfp = (u >> 7) & 3, wn = (u >> 9) & 1;
    int kt = (u >> 10) & 15, nt = u >> 14;
    int c = nt * 128 + wn * 64 + nfp * 16 + (l >> 2);
    int k = kt * 32 + kk * 8 + (l & 3);
    uint4 v;
    v.x = f2tf(W[(size_t)k * NTOT + c]);
    v.y = f2tf(W[(size_t)(k + 4) * NTOT + c]);
    v.z = f2tf(W[(size_t)k * NTOT + c + 8]);
    v.w = f2tf(W[(size_t)(k + 4) * NTOT + c + 8]);
    o[u] = v;
}

// Scatter into packed-A layout (proj input, from attention epilogue).
DEVI void store_attn_packed(int m, int c, float val) {
    int mt = m >> 7, rr = m & 127;
    int wm = rr >> 5, mf = (rr >> 4) & 1, r8 = rr & 15;
    int e0 = r8 >> 3, lhi = r8 & 7;
    int kt = c >> 5, c5 = c & 31, kk = c5 >> 3, cm = c5 & 7;
    int e1 = cm >> 2, llo = cm & 3;
    size_t u = ((size_t)(mt * 16 + kt)) * 1024 + wm * 256 + mf * 128 + kk * 32 + lhi * 4 + llo;
    g_attn[u * 4 + e1 * 2 + e0] = val;
}

// ---------------------------------------------------------------------------
// Attention fragment scatters (from qkv GEMM epilogue). All values tf32-rounded.
// Q: A-frag per (bs, qt(4), kt(16)): u = wm*256+mf*128+kk*32+g*4+t  (512 uint4)
// K: B-frag, k=channel: per (bs, kt(16), jg(32), kh(2)): 32 uint4/unit
//    uint4 = {(j, k), (j, k+4), (j, k+8), (j, k+12)}, k = kt*32+kh*16+t
// V: B-frag, k=block:  per (bs, jt(8), cg(64), jh(2)): 32 uint4/unit
//    uint4 = {(c, j), (c, j+4), (c, j+8), (c, j+12)}, j = jt*32+jh*16+t
// ---------------------------------------------------------------------------
DEVI void scatter_q(int bs, int i, int c, float val) {
    int qt = i >> 6, ri = i & 63;
    int wm = ri >> 5, mf = (ri >> 4) & 1, e0 = (ri >> 3) & 1, g = ri & 7;
    int kt = c >> 5, ck = c & 31, kk = ck >> 3, e1 = (ck >> 2) & 1, t = ck & 3;
    size_t u = ((size_t)((bs * 4 + qt) * 16 + kt)) * 512 + wm * 256 + mf * 128 + kk * 32 + g * 4 + t;
    g_q[u * 4 + e1 * 2 + e0] = val;
}
DEVI void scatter_k(int bs, int j, int c, float val) {
    int kt = c >> 5, ck = c & 31, kh = ck >> 4, cr = ck & 15;
    int elem = cr >> 2, t = cr & 3;
    size_t u = ((size_t)(((bs * 16 + kt) * 32 + (j >> 3)) * 2 + kh)) * 32 + (j & 7) * 4 + t;
    g_k[u * 4 + elem] = val;
}
DEVI void scatter_v(int bs, int j, int c, float val) {
    int jt = j >> 5, jk = j & 31, jh = jk >> 4, jr = jk & 15;
    int elem = jr >> 2, t = jr & 3;
    size_t u = ((size_t)(((bs * 8 + jt) * 64 + (c >> 3)) * 2 + jh)) * 32 + (c & 7) * 4 + t;
    g_v[u * 4 + elem] = val;
}

// ---------------------------------------------------------------------------
// tf32 GEMM, CTA 128x256, warp tile 64x64 (2x4 warps), 3-stage cp.async.
// EPI==0: qkv -> scatter Q/K/V fragment layouts.  EPI==1: row-major out.
// ---------------------------------------------------------------------------
template <int EPI>
__global__ void __launch_bounds__(256) tc_gemm(
    const uint4* __restrict__ Apk, const uint4* __restrict__ Bpk,
    const float* __restrict__ bias, float* __restrict__ out)
{
    extern __shared__ unsigned char sm[];
    const uint32_t smb = smem_u32(sm);
    const int tid = threadIdx.x, lane = tid & 31, wid = tid >> 5;
    const int wm = wid & 1, wn = wid >> 1;           // 2 x 4
    const int nt = blockIdx.x, mt = blockIdx.y;

    const uint4* Ag = Apk + (size_t)mt * 16384;
    const uint4* Bg = Bpk + (size_t)nt * 32768;      // two 128-col subtiles

    auto load_tile = [&](int kt, int s) {
        const uint32_t dst = smb + s * 49152;
#pragma unroll
        for (int i = 0; i < 4; i++) {
            int u = tid + i * 256;
            cp16(dst + u * 16, Ag + kt * 1024 + u);
        }
#pragma unroll
        for (int i = 0; i < 4; i++) {
            int u = tid + i * 256;
            cp16(dst + 16384 + u * 16, Bg + kt * 1024 + u);
        }
#pragma unroll
        for (int i = 0; i < 4; i++) {
            int u = tid + i * 256;
            cp16(dst + 32768 + u * 16, Bg + 16384 + kt * 1024 + u);
        }
        cp_commit();
    };

    float acc[4][8][4];
#pragma unroll
    for (int mf = 0; mf < 4; mf++)
#pragma unroll
        for (int nf = 0; nf < 8; nf++)
#pragma unroll
            for (int r = 0; r < 4; r++) acc[mf][nf][r] = 0.f;

    load_tile(0, 0);
    load_tile(1, 1);

    for (int kt = 0; kt < 16; kt++) {
        if (kt < 15) cp_wait<1>(); else cp_wait<0>();
        __syncthreads();
        if (kt + 2 < 16) load_tile(kt + 2, (kt + 2) % 3);

        const uint32_t st = smb + (kt % 3) * 49152;
        // A frag (wm, mf 0..3): row = wm*64 + mf*16 -> old (wmo = wm*2+(mf>>1), mfo = mf&1)
        const uint32_t aB = st + wm * 8192 + lane * 16;
        // B frag: sub = wn>>1, wno = wn&1
        const uint32_t bB = st + 16384 + (wn >> 1) * 16384 + (wn & 1) * 8192 + lane * 16;
#pragma unroll
        for (int kk = 0; kk < 4; kk++) {
            uint4 a[4], b[4];
#pragma unroll
            for (int mf = 0; mf < 4; mf++)
                a[mf] = lds128(aB + (mf >> 1) * 4096 + (mf & 1) * 2048 + kk * 512);
#pragma unroll
            for (int nfp = 0; nfp < 4; nfp++)
                b[nfp] = lds128(bB + nfp * 2048 + kk * 512);
#pragma unroll
            for (int mf = 0; mf < 4; mf++)
#pragma unroll
                for (int nfp = 0; nfp < 4; nfp++) {
                    mma8(acc[mf][nfp * 2], a[mf], b[nfp].x, b[nfp].y);
                    mma8(acc[mf][nfp * 2 + 1], a[mf], b[nfp].z, b[nfp].w);
                }
        }
    }

#pragma unroll
    for (int mf = 0; mf < 4; mf++)
#pragma unroll
        for (int nf = 0; nf < 8; nf++)
#pragma unroll
            for (int r = 0; r < 4; r++) {
                int row = mt * 128 + wm * 64 + mf * 16 + (lane >> 2) + ((r & 2) ? 8 : 0);
                int cc = nt * 256 + wn * 64 + nf * 8 + (lane & 3) * 2 + (r & 1);
                float v = acc[mf][nf][r] + bias[cc];
                if (EPI == 0) {
                    int b = row >> 13, n = row & 8191;
                    int j = n >> 5, s = n & 31;
                    int bs = b * 32 + s;
                    int hh = cc / 192, rr = cc - hh * 192;
                    int kind = rr >> 6, c = hh * 64 + (rr & 63);
                    float vr = f2tff(v);
                    if (kind == 0) scatter_q(bs, j, c, vr);
                    else if (kind == 1) scatter_k(bs, j, c, vr);
                    else scatter_v(bs, j, c, vr);
                } else {
                    out[(size_t)row * 512 + cc] = v;
                }
            }
}

// ---------------------------------------------------------------------------
// Banded attention, fragment-direct. Grid (2, 256). Warps 2(M) x 4(N).
// ---------------------------------------------------------------------------
template <int W>
__global__ void __launch_bounds__(256, 2) attn_kernel()
{
    constexpr int NF1 = W / 32;
    constexpr int SST = W + 4;

    extern __shared__ unsigned char smraw[];
    float* Ss = (float*)smraw;          // [64][SST]
    unsigned* Sp = (unsigned*)smraw;    // tf32 alias of P

    const int tid = threadIdx.x, lane = tid & 31, wid = tid >> 5;
    const int wm = wid & 1, wn = wid >> 1;
    const int bs = blockIdx.y;
    const int qt = (W == 128) ? (blockIdx.x ? 3 : 0) : (1 + blockIdx.x);
    const int i0 = qt * 64;
    const int jlo = (i0 >= 64) ? (i0 - 64) : 0;

    const uint4* q4 = (const uint4*)g_q + (size_t)(bs * 4 + qt) * 8192;
    const uint4* k4 = (const uint4*)g_k + (size_t)bs * 32768;
    const uint4* v4 = (const uint4*)g_v + (size_t)bs * 32768;

    // ---------------- phase 1: S = Q K^T ----------------
    float acc[2][NF1][4];
#pragma unroll
    for (int mf = 0; mf < 2; mf++)
#pragma unroll
        for (int nf = 0; nf < NF1; nf++)
#pragma unroll
            for (int r = 0; r < 4; r++) acc[mf][nf][r] = 0.f;

    const int jgbase = (jlo >> 3) + wn * (W / 32);

    for (int kt = 0; kt < 16; kt++) {
        const uint4* qk = q4 + kt * 512 + wm * 256 + lane;
        const uint4* kb = k4 + (size_t)(kt * 32 + jgbase) * 64 + lane;
#pragma unroll
        for (int kh = 0; kh < 2; kh++) {
            uint4 ku[NF1];
#pragma unroll
            for (int nf = 0; nf < NF1; nf++) ku[nf] = kb[nf * 64 + kh * 32];
#pragma unroll
            for (int k2 = 0; k2 < 2; k2++) {
                const int kk = kh * 2 + k2;
                uint4 qa0 = qk[kk * 32];
                uint4 qa1 = qk[128 + kk * 32];
#pragma unroll
                for (int nf = 0; nf < NF1; nf++) {
                    unsigned b0 = k2 ? ku[nf].z : ku[nf].x;
                    unsigned b1 = k2 ? ku[nf].w : ku[nf].y;
                    mma8(acc[0][nf], qa0, b0, b1);
                    mma8(acc[1][nf], qa1, b0, b1);
                }
            }
        }
    }

    // scale + band mask + store S to smem
#pragma unroll
    for (int mf = 0; mf < 2; mf++)
#pragma unroll
        for (int nf = 0; nf < NF1; nf++)
#pragma unroll
            for (int r = 0; r < 4; r++) {
                int row = wm * 32 + mf * 16 + (lane >> 2) + ((r & 2) ? 8 : 0);
                int jl = wn * (W / 4) + nf * 8 + (lane & 3) * 2 + (r & 1);
                int i = i0 + row, j = jlo + jl;
                float v = acc[mf][nf][r] * 0.125f;
                if (j < i - 64 || j > i + 64) v = -3.0e38f;
                Ss[row * SST + jl] = v;
            }
    __syncthreads();

    // fp32 softmax: 4 threads per row; write tf32 P in place
    {
        const int row = tid >> 2, part = tid & 3;
        float* rp = Ss + row * SST;
        float mx = -3.4e38f;
        for (int jl = part; jl < W; jl += 4) mx = fmaxf(mx, rp[jl]);
        mx = fmaxf(mx, __shfl_xor_sync(0xffffffffu, mx, 1));
        mx = fmaxf(mx, __shfl_xor_sync(0xffffffffu, mx, 2));
        float sm = 0.f;
        for (int jl = part; jl < W; jl += 4) {
            float e = __expf(rp[jl] - mx);
            rp[jl] = e;
            sm += e;
        }
        sm += __shfl_xor_sync(0xffffffffu, sm, 1);
        sm += __shfl_xor_sync(0xffffffffu, sm, 2);
        float inv = 1.0f / sm;
        unsigned* up = Sp + row * SST;
        for (int jl = part; jl < W; jl += 4) up[jl] = f2tf(rp[jl] * inv);
    }
    __syncthreads();

    // ---------------- phase 2: O = P V ----------------
    const int b = bs >> 5, s = bs & 31;
    const int jt0 = jlo >> 5;

    for (int half = 0; half < 2; half++) {
        float acc2[2][8][4];
#pragma unroll
        for (int mf = 0; mf < 2; mf++)
#pragma unroll
            for (int nf = 0; nf < 8; nf++)
#pragma unroll
                for (int r = 0; r < 4; r++) acc2[mf][nf][r] = 0.f;

        const int cg0 = half * 32 + wn * 8;

        for (int kt2 = 0; kt2 < NF1; kt2++) {
            const uint4* vb = v4 + (size_t)((jt0 + kt2) * 64 + cg0) * 64 + lane;
#pragma unroll
            for (int jh = 0; jh < 2; jh++) {
                uint4 vu[8];
#pragma unroll
                for (int nf = 0; nf < 8; nf++) vu[nf] = vb[nf * 64 + jh * 32];
#pragma unroll
                for (int k2 = 0; k2 < 2; k2++) {
                    const int kk = jh * 2 + k2;
                    const int kA = kt2 * 32 + kk * 8 + (lane & 3);
                    uint4 af[2];
#pragma unroll
                    for (int mf = 0; mf < 2; mf++) {
                        int row = wm * 32 + mf * 16 + (lane >> 2);
                        af[mf].x = Sp[row * SST + kA];
                        af[mf].y = Sp[(row + 8) * SST + kA];
                        af[mf].z = Sp[row * SST + kA + 4];
                        af[mf].w = Sp[(row + 8) * SST + kA + 4];
                    }
#pragma unroll
                    for (int nf = 0; nf < 8; nf++) {
                        unsigned b0 = k2 ? vu[nf].z : vu[nf].x;
                        unsigned b1 = k2 ? vu[nf].w : vu[nf].y;
                        mma8(acc2[0][nf], af[0], b0, b1);
                        mma8(acc2[1][nf], af[1], b0, b1);
                    }
                }
            }
        }

#pragma unroll
        for (int mf = 0; mf < 2; mf++)
#pragma unroll
            for (int nf = 0; nf < 8; nf++)
#pragma unroll
                for (int r = 0; r < 4; r++) {
                    int row = wm * 32 + mf * 16 + (lane >> 2) + ((r & 2) ? 8 : 0);
                    int c = half * 256 + wn * 64 + nf * 8 + (lane & 3) * 2 + (r & 1);
                    int m = b * 8192 + (i0 + row) * 32 + s;
                    store_attn_packed(m, c, f2tff(acc2[mf][nf][r]));
                }
    }
}

// ---------------------------------------------------------------------------
extern "C" void kernel_launch(void* const* d_in, const int* in_sizes, int n_in,
                              void* d_out, int out_size)
{
    const float* x  = (const float*)d_in[0];
    const float* Wq = (const float*)d_in[1];
    const float* bq = (const float*)d_in[2];
    const float* Wp = (const float*)d_in[3];
    const float* bp = (const float*)d_in[4];
    float* out = (float*)d_out;

    void *pxr, *pwq, *pwp, *pattn;
    cudaGetSymbolAddress(&pxr, g_xr);
    cudaGetSymbolAddress(&pwq, g_wq);
    cudaGetSymbolAddress(&pwp, g_wp);
    cudaGetSymbolAddress(&pattn, g_attn);

    const int smG = 3 * 49152;            // 147456
    const int smA128 = 64 * 132 * 4;      // 33792
    const int smA192 = 64 * 196 * 4;      // 50176

    cudaFuncSetAttribute(tc_gemm<0>, cudaFuncAttributeMaxDynamicSharedMemorySize, smG);
    cudaFuncSetAttribute(tc_gemm<1>, cudaFuncAttributeMaxDynamicSharedMemorySize, smG);
    cudaFuncSetAttribute(attn_kernel<128>, cudaFuncAttributeMaxDynamicSharedMemorySize, smA128);
    cudaFuncSetAttribute(attn_kernel<192>, cudaFuncAttributeMaxDynamicSharedMemorySize, smA192);

    // 0) pack + tf32-round operands into fragment order
    pack_x<<<32768, 256>>>(x, (uint4*)pxr);
    pack_w<1536><<<768, 256>>>(Wq, (uint4*)pwq);
    pack_w<512><<<256, 256>>>(Wp, (uint4*)pwp);

    // 1) QKV projection + fragment scatter into g_q/g_k/g_v
    tc_gemm<0><<<dim3(6, 512), 256, smG>>>((const uint4*)pxr, (const uint4*)pwq, bq, nullptr);

    // 2) banded attention (fragment-direct; writes packed g_attn)
    attn_kernel<128><<<dim3(2, 256), 256, smA128>>>();
    attn_kernel<192><<<dim3(2, 256), 256, smA192>>>();

    // 3) output projection
    tc_gemm<1><<<dim3(2, 512), 256, smG>>>((const uint4*)pattn, (const uint4*)pwp, bp, out);
}

// round 5
// speedup vs baseline: 1.8595x; 1.8595x over previous
#include <cuda_runtime.h>
#include <cuda_fp16.h>
#include <cstdint>

#define DEVI __device__ __forceinline__

// ---------------------------------------------------------------------------
// Scratch (device globals; aliased as fp16 where noted)
// ---------------------------------------------------------------------------
__device__ float g_q[33554432];     // [bs][j][c] canonical fp32
__device__ float g_k[33554432];
__device__ float g_v[33554432];
__device__ float g_attn[33554432];  // aliased __half: attention out, packed A-frags
__device__ float g_xr[33554432];    // aliased __half: x packed A-frags
__device__ float g_wq[786432];      // aliased __half: W_qkv packed B-frags
__device__ float g_wp[262144];      // aliased __half: W_proj packed B-frags

DEVI unsigned f2tf(float f) {
    unsigned u;
    asm("cvt.rna.tf32.f32 %0, %1;" : "=r"(u) : "f"(f));
    return u;
}

DEVI uint32_t smem_u32(const void* p) {
    uint32_t a;
    asm("{ .reg .u64 t; cvta.to.shared.u64 t, %1; cvt.u32.u64 %0, t; }" : "=r"(a) : "l"(p));
    return a;
}
DEVI uint4 lds128(uint32_t a) {
    uint4 v;
    asm volatile("ld.shared.v4.u32 {%0,%1,%2,%3}, [%4];"
                 : "=r"(v.x), "=r"(v.y), "=r"(v.z), "=r"(v.w) : "r"(a));
    return v;
}
DEVI void cp16(uint32_t s, const void* g) {
    asm volatile("cp.async.cg.shared.global [%0], [%1], 16;" :: "r"(s), "l"(g));
}
DEVI void cp_commit() { asm volatile("cp.async.commit_group;"); }
template <int N> DEVI void cp_wait() { asm volatile("cp.async.wait_group %0;" :: "n"(N)); }

// fp16 mma m16n8k16, fp32 accum
DEVI void mma16(float* d, const uint4& a, unsigned b0, unsigned b1) {
    asm("mma.sync.aligned.m16n8k16.row.col.f32.f16.f16.f32 "
        "{%0,%1,%2,%3}, {%4,%5,%6,%7}, {%8,%9}, {%0,%1,%2,%3};"
        : "+f"(d[0]), "+f"(d[1]), "+f"(d[2]), "+f"(d[3])
        : "r"(a.x), "r"(a.y), "r"(a.z), "r"(a.w), "r"(b0), "r"(b1));
}
// tf32 mma m16n8k8 (attention, proven R3 path)
DEVI void mma8a(float* d, const unsigned* a, const unsigned* b) {
    asm("mma.sync.aligned.m16n8k8.row.col.f32.tf32.tf32.f32 "
        "{%0,%1,%2,%3}, {%4,%5,%6,%7}, {%8,%9}, {%0,%1,%2,%3};"
        : "+f"(d[0]), "+f"(d[1]), "+f"(d[2]), "+f"(d[3])
        : "r"(a[0]), "r"(a[1]), "r"(a[2]), "r"(a[3]), "r"(b[0]), "r"(b[1]));
}

DEVI unsigned pack2(float lo, float hi) {
    __half2 h = __floats2half2_rn(lo, hi);
    return *(unsigned*)&h;
}

// ---------------------------------------------------------------------------
// fp16 fragment packs. Per (128-tile, ktile of 32 k): 512 uint4 = 8KB.
// A unit u = wm*128 + mf*64 + kk*32 + l ;  r0 = wm*32+mf*16+(l>>2), k0 = kk*16+(l&3)*2
//   uint4 = { (r0,k0|k0+1), (r0+8,k0|k0+1), (r0,k0+8|k0+9), (r0+8,k0+8|k0+9) }
// B unit u = wn*256 + nfp*64 + kk*32 + l ; c = wn*64+nfp*16+(l>>2), k0 as above
//   uint4 = { (k0|k0+1,c), (k0+8|k0+9,c), (k0|k0+1,c+8), (k0+8|k0+9,c+8) }
// ---------------------------------------------------------------------------
__global__ void pack_x(const float* __restrict__ x, uint4* __restrict__ o) {
    int u = blockIdx.x * 256 + threadIdx.x;
    int l = u & 31, kk = (u >> 5) & 1, mf = (u >> 6) & 1, wm = (u >> 7) & 3;
    int kt = (u >> 9) & 15, mt = u >> 13;
    int r = mt * 128 + wm * 32 + mf * 16 + (l >> 2);
    int k = kt * 32 + kk * 16 + (l & 3) * 2;
    const float* p = x + (size_t)r * 512 + k;
    uint4 v;
    v.x = pack2(p[0], p[1]);
    v.y = pack2(p[8 * 512], p[8 * 512 + 1]);
    v.z = pack2(p[8], p[9]);
    v.w = pack2(p[8 * 512 + 8], p[8 * 512 + 9]);
    o[u] = v;
}

template <int NTOT>
__global__ void pack_w(const float* __restrict__ W, uint4* __restrict__ o) {
    int u = blockIdx.x * 256 + threadIdx.x;
    int l = u & 31, kk = (u >> 5) & 1, nfp = (u >> 6) & 3, wn = (u >> 8) & 1;
    int kt = (u >> 9) & 15, nt = u >> 13;
    int c = nt * 128 + wn * 64 + nfp * 16 + (l >> 2);
    int k = kt * 32 + kk * 16 + (l & 3) * 2;
    uint4 v;
    v.x = pack2(W[(size_t)k * NTOT + c], W[(size_t)(k + 1) * NTOT + c]);
    v.y = pack2(W[(size_t)(k + 8) * NTOT + c], W[(size_t)(k + 9) * NTOT + c]);
    v.z = pack2(W[(size_t)k * NTOT + c + 8], W[(size_t)(k + 1) * NTOT + c + 8]);
    v.w = pack2(W[(size_t)(k + 8) * NTOT + c + 8], W[(size_t)(k + 9) * NTOT + c + 8]);
    o[u] = v;
}

// Scatter one fp16 value into packed-A layout (attention epilogue -> proj input).
DEVI void store_attn_packed_h(int m, int c, float val) {
    int mt = m >> 7, rr = m & 127;
    int wm = rr >> 5, mf = (rr >> 4) & 1, e0 = (rr >> 3) & 1, g = rr & 7;
    int kt = c >> 5, ck = c & 31;
    int kk = (ck >> 4) & 1, e1 = (ck >> 3) & 1, t = (ck >> 1) & 3, par = ck & 1;
    size_t u = ((size_t)(mt * 16 + kt)) * 512 + wm * 128 + mf * 64 + kk * 32 + g * 4 + t;
    ((__half*)g_attn)[(u * 4 + e1 * 2 + e0) * 2 + par] = __float2half_rn(val);
}

// ---------------------------------------------------------------------------
// fp16 GEMM: CTA 128x128, warps 4(M)x2(N), warp tile 32x64, 3-stage cp.async.
// EPI==0: qkv -> canonical g_q/g_k/g_v scatter.  EPI==1: row-major fp32 out.
// ---------------------------------------------------------------------------
template <int EPI>
__global__ void __launch_bounds__(256, 2) tc_gemm(
    const uint4* __restrict__ Apk, const uint4* __restrict__ Bpk,
    const float* __restrict__ bias, float* __restrict__ out)
{
    extern __shared__ unsigned char sm[];
    const uint32_t smb = smem_u32(sm);
    const int tid = threadIdx.x, lane = tid & 31, wid = tid >> 5;
    const int wm = wid & 3, wn = wid >> 2;
    const int nt = blockIdx.x, mt = blockIdx.y;

    const uint4* Ag = Apk + (size_t)mt * 8192;   // 16 ktiles * 512 units
    const uint4* Bg = Bpk + (size_t)nt * 8192;

    auto load_tile = [&](int kt, int s) {
        const uint32_t dst = smb + s * 16384;
        const uint4* sa = Ag + kt * 512;
        const uint4* sb = Bg + kt * 512;
        cp16(dst + tid * 16, sa + tid);
        cp16(dst + (tid + 256) * 16, sa + tid + 256);
        cp16(dst + 8192 + tid * 16, sb + tid);
        cp16(dst + 8192 + (tid + 256) * 16, sb + tid + 256);
        cp_commit();
    };

    float acc[2][8][4];
#pragma unroll
    for (int mf = 0; mf < 2; mf++)
#pragma unroll
        for (int nf = 0; nf < 8; nf++)
#pragma unroll
            for (int r = 0; r < 4; r++) acc[mf][nf][r] = 0.f;

    load_tile(0, 0);
    load_tile(1, 1);

    for (int kt = 0; kt < 16; kt++) {
        if (kt < 15) cp_wait<1>(); else cp_wait<0>();
        __syncthreads();
        if (kt + 2 < 16) load_tile(kt + 2, (kt + 2) % 3);

        const uint32_t st = smb + (kt % 3) * 16384;
        const uint32_t aB = st + (wm * 128 + lane) * 16;
        const uint32_t bB = st + 8192 + (wn * 256 + lane) * 16;
#pragma unroll
        for (int kk = 0; kk < 2; kk++) {
            uint4 a0 = lds128(aB + kk * 512);
            uint4 a1 = lds128(aB + 1024 + kk * 512);
            uint4 b0 = lds128(bB + kk * 512);
            uint4 b1 = lds128(bB + 1024 + kk * 512);
            uint4 b2 = lds128(bB + 2048 + kk * 512);
            uint4 b3 = lds128(bB + 3072 + kk * 512);
            mma16(acc[0][0], a0, b0.x, b0.y);
            mma16(acc[0][1], a0, b0.z, b0.w);
            mma16(acc[0][2], a0, b1.x, b1.y);
            mma16(acc[0][3], a0, b1.z, b1.w);
            mma16(acc[0][4], a0, b2.x, b2.y);
            mma16(acc[0][5], a0, b2.z, b2.w);
            mma16(acc[0][6], a0, b3.x, b3.y);
            mma16(acc[0][7], a0, b3.z, b3.w);
            mma16(acc[1][0], a1, b0.x, b0.y);
            mma16(acc[1][1], a1, b0.z, b0.w);
            mma16(acc[1][2], a1, b1.x, b1.y);
            mma16(acc[1][3], a1, b1.z, b1.w);
            mma16(acc[1][4], a1, b2.x, b2.y);
            mma16(acc[1][5], a1, b2.z, b2.w);
            mma16(acc[1][6], a1, b3.x, b3.y);
            mma16(acc[1][7], a1, b3.z, b3.w);
        }
    }

    // epilogue: D frag d0=(g,2t) d1=(g,2t+1) d2=(g+8,2t) d3=(g+8,2t+1)
#pragma unroll
    for (int mf = 0; mf < 2; mf++)
#pragma unroll
        for (int nf = 0; nf < 8; nf++)
#pragma unroll
            for (int r = 0; r < 4; r++) {
                int row = mt * 128 + wm * 32 + mf * 16 + (lane >> 2) + ((r & 2) ? 8 : 0);
                int cc = nt * 128 + wn * 64 + nf * 8 + (lane & 3) * 2 + (r & 1);
                float v = acc[mf][nf][r] + bias[cc];
                if (EPI == 0) {
                    int b = row >> 13, n = row & 8191;
                    int j = n >> 5, s = n & 31;
                    int hh = cc / 192, rr = cc - hh * 192;
                    int kind = rr >> 6, d = rr & 63;
                    int c = hh * 64 + d;
                    int dst = ((b * 32 + s) * 256 + j) * 512 + c;
                    float* dp = (kind == 0) ? g_q : (kind == 1) ? g_k : g_v;
                    dp[dst] = v;
                } else {
                    out[(size_t)row * 512 + cc] = v;
                }
            }
}

// ---------------------------------------------------------------------------
// Banded attention: R3-proven tf32 path. Epilogue writes fp16-packed g_attn.
// ---------------------------------------------------------------------------
template <int W>
__global__ void __launch_bounds__(256) attn_kernel()
{
    constexpr int NF1 = W / 32;
    constexpr int SST = W + 4;

    extern __shared__ unsigned char smraw[];
    float* Ss = (float*)smraw;
    unsigned* Sp = (unsigned*)smraw;
    unsigned* Qs = (unsigned*)(smraw + 64 * SST * 4);
    unsigned* Ks = Qs + 2 * 64 * 36;
    unsigned* Vs = Qs;

    const int tid = threadIdx.x, lane = tid & 31, wid = tid >> 5;
    const int bs = blockIdx.y;
    const int qt = (W == 128) ? (blockIdx.x ? 3 : 0) : (1 + blockIdx.x);
    const int i0 = qt * 64;
    const int jlo = (i0 >= 64) ? (i0 - 64) : 0;

    const float* Qg = g_q + (size_t)(bs * 256 + i0) * 512;
    const float* Kg = g_k + (size_t)(bs * 256 + jlo) * 512;
    const float* Vg = g_v + (size_t)(bs * 256 + jlo) * 512;

    const int wm = wid & 1, wn = wid >> 1;

    float4 rq[2], rk[NF1];
    auto ldg1 = [&](int kt) {
        const int k0 = kt * 32;
#pragma unroll
        for (int i = 0; i < 2; i++) {
            int lin = tid + i * 256;
            rq[i] = *(const float4*)(Qg + (lin >> 3) * 512 + k0 + (lin & 7) * 4);
        }
#pragma unroll
        for (int i = 0; i < NF1; i++) {
            int lin = tid + i * 256;
            rk[i] = *(const float4*)(Kg + (lin >> 3) * 512 + k0 + (lin & 7) * 4);
        }
    };
    auto sts1 = [&](int buf) {
#pragma unroll
        for (int i = 0; i < 2; i++) {
            int lin = tid + i * 256;
            uint4 t = make_uint4(f2tf(rq[i].x), f2tf(rq[i].y), f2tf(rq[i].z), f2tf(rq[i].w));
            *(uint4*)&Qs[buf * 2304 + (lin >> 3) * 36 + (lin & 7) * 4] = t;
        }
#pragma unroll
        for (int i = 0; i < NF1; i++) {
            int lin = tid + i * 256;
            uint4 t = make_uint4(f2tf(rk[i].x), f2tf(rk[i].y), f2tf(rk[i].z), f2tf(rk[i].w));
            *(uint4*)&Ks[buf * (W * 36) + (lin >> 3) * 36 + (lin & 7) * 4] = t;
        }
    };

    float acc[2][NF1][4];
#pragma unroll
    for (int mf = 0; mf < 2; mf++)
#pragma unroll
        for (int nf = 0; nf < NF1; nf++)
#pragma unroll
            for (int r = 0; r < 4; r++) acc[mf][nf][r] = 0.f;

    ldg1(0);
    sts1(0);
    __syncthreads();

    for (int kt = 0; kt < 16; kt++) {
        if (kt < 15) ldg1(kt + 1);
        const int buf = kt & 1;
#pragma unroll
        for (int kk = 0; kk < 4; kk++) {
            const int k = kk * 8 + (lane & 3);
            unsigned af[2][4], bf[NF1][2];
#pragma unroll
            for (int mf = 0; mf < 2; mf++) {
                int row = wm * 32 + mf * 16 + (lane >> 2);
                const unsigned* p = &Qs[buf * 2304 + row * 36 + k];
                af[mf][0] = p[0];
                af[mf][1] = p[8 * 36];
                af[mf][2] = p[4];
                af[mf][3] = p[8 * 36 + 4];
            }
#pragma unroll
            for (int nf = 0; nf < NF1; nf++) {
                int col = wn * (W / 4) + nf * 8 + (lane >> 2);
                const unsigned* p = &Ks[buf * (W * 36) + col * 36 + k];
                bf[nf][0] = p[0];
                bf[nf][1] = p[4];
            }
#pragma unroll
            for (int mf = 0; mf < 2; mf++)
#pragma unroll
                for (int nf = 0; nf < NF1; nf++)
                    mma8a(acc[mf][nf], af[mf], bf[nf]);
        }
        if (kt < 15) sts1(buf ^ 1);
        __syncthreads();
    }

#pragma unroll
    for (int mf = 0; mf < 2; mf++)
#pragma unroll
        for (int nf = 0; nf < NF1; nf++)
#pragma unroll
            for (int r = 0; r < 4; r++) {
                int row = wm * 32 + mf * 16 + (lane >> 2) + ((r & 2) ? 8 : 0);
                int jl = wn * (W / 4) + nf * 8 + (lane & 3) * 2 + (r & 1);
                int i = i0 + row, j = jlo + jl;
                float v = acc[mf][nf][r] * 0.125f;
                if (j < i - 64 || j > i + 64) v = -3.0e38f;
                Ss[row * SST + jl] = v;
            }
    __syncthreads();

    {
        const int row = tid >> 2, part = tid & 3;
        float* rp = Ss + row * SST;
        float mx = -3.4e38f;
        for (int jl = part; jl < W; jl += 4) mx = fmaxf(mx, rp[jl]);
        mx = fmaxf(mx, __shfl_xor_sync(0xffffffffu, mx, 1));
        mx = fmaxf(mx, __shfl_xor_sync(0xffffffffu, mx, 2));
        float sm = 0.f;
        for (int jl = part; jl < W; jl += 4) {
            float e = __expf(rp[jl] - mx);
            rp[jl] = e;
            sm += e;
        }
        sm += __shfl_xor_sync(0xffffffffu, sm, 1);
        sm += __shfl_xor_sync(0xffffffffu, sm, 2);
        float inv = 1.0f / sm;
        unsigned* up = Sp + row * SST;
        for (int jl = part; jl < W; jl += 4) up[jl] = f2tf(rp[jl] * inv);
    }
    __syncthreads();

    const int b = bs >> 5, s = bs & 31;
    for (int half = 0; half < 2; half++) {
        float acc2[2][8][4];
#pragma unroll
        for (int mf = 0; mf < 2; mf++)
#pragma unroll
            for (int nf = 0; nf < 8; nf++)
#pragma unroll
                for (int r = 0; r < 4; r++) acc2[mf][nf][r] = 0.f;

        float4 rv[8];
        auto ldg2 = [&](int kt) {
#pragma unroll
            for (int i = 0; i < 8; i++) {
                int lin = tid + i * 256;
                rv[i] = *(const float4*)(Vg + (size_t)(kt * 32 + (lin >> 6)) * 512 +
                                          half * 256 + (lin & 63) * 4);
            }
        };
        auto sts2 = [&](int buf) {
#pragma unroll
            for (int i = 0; i < 8; i++) {
                int lin = tid + i * 256;
                uint4 t = make_uint4(f2tf(rv[i].x), f2tf(rv[i].y), f2tf(rv[i].z), f2tf(rv[i].w));
                *(uint4*)&Vs[buf * 8320 + (lin >> 6) * 260 + (lin & 63) * 4] = t;
            }
        };

        ldg2(0);
        sts2(0);
        __syncthreads();

        for (int kt = 0; kt < NF1; kt++) {
            if (kt < NF1 - 1) ldg2(kt + 1);
            const int buf = kt & 1;
#pragma unroll
            for (int kk = 0; kk < 4; kk++) {
                const int kA = kt * 32 + kk * 8 + (lane & 3);
                const int kl = kk * 8 + (lane & 3);
                unsigned af[2][4], bf[8][2];
#pragma unroll
                for (int mf = 0; mf < 2; mf++) {
                    int row = wm * 32 + mf * 16 + (lane >> 2);
                    af[mf][0] = Sp[row * SST + kA];
                    af[mf][1] = Sp[(row + 8) * SST + kA];
                    af[mf][2] = Sp[row * SST + kA + 4];
                    af[mf][3] = Sp[(row + 8) * SST + kA + 4];
                }
#pragma unroll
                for (int nf = 0; nf < 8; nf++) {
                    int col = wn * 64 + nf * 8 + (lane >> 2);
                    bf[nf][0] = Vs[buf * 8320 + kl * 260 + col];
                    bf[nf][1] = Vs[buf * 8320 + (kl + 4) * 260 + col];
                }
#pragma unroll
                for (int mf = 0; mf < 2; mf++)
#pragma unroll
                    for (int nf = 0; nf < 8; nf++)
                        mma8a(acc2[mf][nf], af[mf], bf[nf]);
            }
            if (kt < NF1 - 1) sts2(buf ^ 1);
            __syncthreads();
        }

#pragma unroll
        for (int mf = 0; mf < 2; mf++)
#pragma unroll
            for (int nf = 0; nf < 8; nf++)
#pragma unroll
                for (int r = 0; r < 4; r++) {
                    int row = wm * 32 + mf * 16 + (lane >> 2) + ((r & 2) ? 8 : 0);
                    int c = half * 256 + wn * 64 + nf * 8 + (lane & 3) * 2 + (r & 1);
                    int m = b * 8192 + (i0 + row) * 32 + s;
                    store_attn_packed_h(m, c, acc2[mf][nf][r]);
                }
        __syncthreads();
    }
}

// ---------------------------------------------------------------------------
extern "C" void kernel_launch(void* const* d_in, const int* in_sizes, int n_in,
                              void* d_out, int out_size)
{
    const float* x  = (const float*)d_in[0];
    const float* Wq = (const float*)d_in[1];
    const float* bq = (const float*)d_in[2];
    const float* Wp = (const float*)d_in[3];
    const float* bp = (const float*)d_in[4];
    float* out = (float*)d_out;

    void *pxr, *pwq, *pwp, *pattn;
    cudaGetSymbolAddress(&pxr, g_xr);
    cudaGetSymbolAddress(&pwq, g_wq);
    cudaGetSymbolAddress(&pwp, g_wp);
    cudaGetSymbolAddress(&pattn, g_attn);

    const int smG = 3 * 16384;                                          // 49152
    const int smA128 = 64 * 132 * 4 + 2 * 32 * 260 * 4;                 // 100352
    const int smA192 = 64 * 196 * 4 + (2 * 64 * 36 + 2 * 192 * 36) * 4; // 123904

    cudaFuncSetAttribute(tc_gemm<0>, cudaFuncAttributeMaxDynamicSharedMemorySize, smG);
    cudaFuncSetAttribute(tc_gemm<1>, cudaFuncAttributeMaxDynamicSharedMemorySize, smG);
    cudaFuncSetAttribute(attn_kernel<128>, cudaFuncAttributeMaxDynamicSharedMemorySize, smA128);
    cudaFuncSetAttribute(attn_kernel<192>, cudaFuncAttributeMaxDynamicSharedMemorySize, smA192);

    // 0) pack + fp16-round operands into m16n8k16 fragment order
    pack_x<<<16384, 256>>>(x, (uint4*)pxr);
    pack_w<1536><<<384, 256>>>(Wq, (uint4*)pwq);
    pack_w<512><<<128, 256>>>(Wp, (uint4*)pwp);

    // 1) QKV projection (fp16 mma) + canonical scatter into g_q/g_k/g_v
    tc_gemm<0><<<dim3(12, 512), 256, smG>>>((const uint4*)pxr, (const uint4*)pwq, bq, nullptr);

    // 2) banded attention (tf32, R3-proven; writes fp16-packed g_attn)
    attn_kernel<128><<<dim3(2, 256), 256, smA128>>>();
    attn_kernel<192><<<dim3(2, 256), 256, smA192>>>();

    // 3) output projection (fp16 mma)
    tc_gemm<1><<<dim3(4, 512), 256, smG>>>((const uint4*)pattn, (const uint4*)pwp, bp, out);
}